// round 15
// baseline (speedup 1.0000x reference)
#include <cuda_runtime.h>
#include <cstdint>

// Embedding gather: out[row, :] = weight[ids[row], :]
// ids: [8192] int32, weight: [32000, 1024] f32, out: [8192, 1024] f32.
//
// R10: same winning structure as the 10.7us kernel (one CTA/row, 256 thr,
// float4), but both the weight load and the output store carry an
// L2::evict_last policy via the createpolicy + L2::cache_hint form (which,
// unlike the bare .L2::evict_last modifier, is legal at v4 width).
// Goal: keep the rewritten-every-replay output dirty-resident in L2 and
// suppress the ~30MB/launch DRAM writeback stream that currently paces the
// kernel.

#define DIM 1024
#define VEC (DIM / 4)   // 256 float4 per row

__device__ __forceinline__ uint64_t evict_last_policy()
{
    uint64_t pol;
    asm("createpolicy.fractional.L2::evict_last.b64 %0, 1.0;" : "=l"(pol));
    return pol;
}

__device__ __forceinline__ float4 ldg_hint(const float4* p, uint64_t pol)
{
    float4 v;
    asm volatile("ld.global.nc.L2::cache_hint.v4.f32 {%0,%1,%2,%3}, [%4], %5;"
                 : "=f"(v.x), "=f"(v.y), "=f"(v.z), "=f"(v.w)
                 : "l"(p), "l"(pol));
    return v;
}

__device__ __forceinline__ void stg_hint(float4* p, float4 v, uint64_t pol)
{
    asm volatile("st.global.L2::cache_hint.v4.f32 [%0], {%1,%2,%3,%4}, %5;"
                 :: "l"(p), "f"(v.x), "f"(v.y), "f"(v.z), "f"(v.w), "l"(pol)
                 : "memory");
}

__global__ void __launch_bounds__(256, 8)
embed_gather_kernel(const int* __restrict__ ids,
                    const float* __restrict__ weight,
                    float* __restrict__ out)
{
    const int row = blockIdx.x;
    const int id  = __ldg(ids + row);

    const uint64_t pol = evict_last_policy();

    const float4* __restrict__ src =
        reinterpret_cast<const float4*>(weight) + (size_t)id * VEC;
    float4* __restrict__ dst =
        reinterpret_cast<float4*>(out) + (size_t)row * VEC;

    const float4 v = ldg_hint(src + threadIdx.x, pol);
    stg_hint(dst + threadIdx.x, v, pol);
}

extern "C" void kernel_launch(void* const* d_in, const int* in_sizes, int n_in,
                              void* d_out, int out_size)
{
    const int*   ids    = (const int*)d_in[0];
    const float* weight = (const float*)d_in[1];
    float*       out    = (float*)d_out;

    const int n_rows = in_sizes[0];   // 8192

    embed_gather_kernel<<<n_rows, 256>>>(ids, weight, out);
}